// round 11
// baseline (speedup 1.0000x reference)
#include <cuda_runtime.h>
#include <cuda_fp8.h>
#include <cstdint>
#include <cstddef>

// ============================================================
// Dims (fixed): x[8192,4096] @ w1[4096,16384] -> relu -> @ w2[16384,4096]
// ============================================================
#define M_DIM 8192
#define DIN   4096
#define DH    16384
#define DOUT  4096

__device__ __align__(16) unsigned char g_xq  [(size_t)M_DIM * DIN];
__device__ __align__(16) unsigned char g_w1qT[(size_t)DH    * DIN];
__device__ __align__(16) unsigned char g_w2qT[(size_t)DOUT  * DH];
__device__ __align__(16) unsigned char g_hq  [(size_t)M_DIM * DH];
__device__ __align__(16) float         g_h   [(size_t)M_DIM * DH];
__device__ float g_amax[4];   // 0:x 1:w1 2:w2 3:h

// ============================================================
// PTX helpers (base sm_103-legal only)
// ============================================================
__device__ __forceinline__ uint32_t smem_u32(const void* p) {
    uint32_t a;
    asm("{ .reg .u64 t; cvta.to.shared.u64 t, %1; cvt.u32.u64 %0, t; }" : "=r"(a) : "l"(p));
    return a;
}

#define CP_ASYNC16(saddr, gptr) \
    asm volatile("cp.async.cg.shared.global [%0], [%1], 16;\n" :: "r"(saddr), "l"(gptr))
#define CP_COMMIT() asm volatile("cp.async.commit_group;\n" ::: "memory")
#define CP_WAIT1()  asm volatile("cp.async.wait_group 1;\n" ::: "memory")

__device__ __forceinline__ void ldsm_x4(uint32_t& r0, uint32_t& r1, uint32_t& r2, uint32_t& r3,
                                        uint32_t addr) {
    asm volatile("ldmatrix.sync.aligned.m8n8.x4.shared.b16 {%0,%1,%2,%3}, [%4];\n"
                 : "=r"(r0), "=r"(r1), "=r"(r2), "=r"(r3) : "r"(addr));
}

__device__ __forceinline__ void mma_e4m3(float* d, const uint32_t* a, const uint32_t* b) {
    asm volatile(
        "mma.sync.aligned.m16n8k32.row.col.f32.e4m3.e4m3.f32 "
        "{%0,%1,%2,%3}, {%4,%5,%6,%7}, {%8,%9}, {%0,%1,%2,%3};\n"
        : "+f"(d[0]), "+f"(d[1]), "+f"(d[2]), "+f"(d[3])
        : "r"(a[0]), "r"(a[1]), "r"(a[2]), "r"(a[3]), "r"(b[0]), "r"(b[1]));
}

// SMEM tile rows of 64B (BK=64); 16B chunk idx XOR-swizzled by (row>>1)&3.
__device__ __forceinline__ uint32_t soff(int r, int c16) {
    return (uint32_t)(r * 64 + (((c16) ^ ((r >> 1) & 3)) << 4));
}

// ============================================================
// init / fused amax / fused prep / quant_h
// ============================================================
__global__ void init_amax_kernel() {
    if (threadIdx.x < 4) g_amax[threadIdx.x] = 0.0f;
}

__device__ __forceinline__ void amax_body(const float4* __restrict__ p4, size_t n4,
                                          int rb, int nb, int slot) {
    float m = 0.f;
    size_t i0 = (size_t)rb * blockDim.x + threadIdx.x;
    size_t stride = (size_t)nb * blockDim.x;
    for (size_t i = i0; i < n4; i += stride) {
        float4 v = __ldcs(p4 + i);
        m = fmaxf(m, fmaxf(fmaxf(fabsf(v.x), fabsf(v.y)), fmaxf(fabsf(v.z), fabsf(v.w))));
    }
    for (int o = 16; o; o >>= 1) m = fmaxf(m, __shfl_xor_sync(0xffffffffu, m, o));
    __shared__ float sm[8];
    if ((threadIdx.x & 31) == 0) sm[threadIdx.x >> 5] = m;
    __syncthreads();
    if (threadIdx.x < 32) {
        m = (threadIdx.x < (blockDim.x >> 5)) ? sm[threadIdx.x] : 0.f;
        for (int o = 16; o; o >>= 1) m = fmaxf(m, __shfl_xor_sync(0xffffffffu, m, o));
        if (threadIdx.x == 0) atomicMax((int*)&g_amax[slot], __float_as_int(m));
    }
}

#define AMAX_BX 320
#define AMAX_BW 640
__global__ void amax3_kernel(const float* __restrict__ x,
                             const float* __restrict__ w1,
                             const float* __restrict__ w2) {
    int b = blockIdx.x;
    if (b < AMAX_BX) {
        amax_body((const float4*)x, (size_t)M_DIM * DIN / 4, b, AMAX_BX, 0);
    } else if (b < AMAX_BX + AMAX_BW) {
        amax_body((const float4*)w1, (size_t)DIN * DH / 4, b - AMAX_BX, AMAX_BW, 1);
    } else {
        amax_body((const float4*)w2, (size_t)DH * DOUT / 4, b - AMAX_BX - AMAX_BW, AMAX_BW, 2);
    }
}

__device__ __forceinline__ void quant_body(const float4* __restrict__ p4,
                                           uint32_t* __restrict__ q4,
                                           size_t n4, int rb, int nb, int slot) {
    float s = 448.0f / fmaxf(g_amax[slot], 1e-12f);
    size_t i0 = (size_t)rb * blockDim.x + threadIdx.x;
    size_t stride = (size_t)nb * blockDim.x;
    for (size_t i = i0; i < n4; i += stride) {
        float4 v = __ldcs(p4 + i);
        __nv_fp8x2_storage_t lo = __nv_cvt_float2_to_fp8x2(make_float2(v.x * s, v.y * s), __NV_SATFINITE, __NV_E4M3);
        __nv_fp8x2_storage_t hi = __nv_cvt_float2_to_fp8x2(make_float2(v.z * s, v.w * s), __NV_SATFINITE, __NV_E4M3);
        q4[i] = (uint32_t)lo | ((uint32_t)hi << 16);
    }
}

__device__ __forceinline__ void quantT_body(const float* __restrict__ w,
                                            unsigned char* __restrict__ qT,
                                            int K, int N, int n0, int k0, int slot) {
    __shared__ float tile[32][33];
    float s = 448.0f / fmaxf(g_amax[slot], 1e-12f);
    int tx = threadIdx.x & 31, ty = threadIdx.x >> 5;
    #pragma unroll
    for (int r = ty; r < 32; r += 8)
        tile[r][tx] = __ldcs(&w[(size_t)(k0 + r) * N + n0 + tx]);
    __syncthreads();
    #pragma unroll
    for (int r = ty; r < 32; r += 8) {
        float v = tile[tx][r] * s;
        qT[(size_t)(n0 + r) * K + k0 + tx] =
            __nv_cvt_float_to_fp8(v, __NV_SATFINITE, __NV_E4M3);
    }
}

#define PREP_QX   1184
#define PREP_W1T  ((DH / 32) * (DIN / 32))
#define PREP_W2T  ((DOUT / 32) * (DH / 32))
#define PREP_BLOCKS (PREP_QX + PREP_W1T + PREP_W2T)

__global__ void prep_kernel(const float* __restrict__ x,
                            const float* __restrict__ w1,
                            const float* __restrict__ w2,
                            unsigned char* __restrict__ xq,
                            unsigned char* __restrict__ w1qT,
                            unsigned char* __restrict__ w2qT) {
    int b = blockIdx.x;
    if (b < PREP_QX) {
        quant_body((const float4*)x, (uint32_t*)xq, (size_t)M_DIM * DIN / 4, b, PREP_QX, 0);
    } else if (b < PREP_QX + PREP_W1T) {
        int t = b - PREP_QX;
        int n0 = (t % (DH / 32)) * 32, k0 = (t / (DH / 32)) * 32;
        quantT_body(w1, w1qT, DIN, DH, n0, k0, 1);
    } else {
        int t = b - PREP_QX - PREP_W1T;
        int n0 = (t % (DOUT / 32)) * 32, k0 = (t / (DOUT / 32)) * 32;
        quantT_body(w2, w2qT, DH, DOUT, n0, k0, 2);
    }
}

__global__ void quant_h_kernel(const float* __restrict__ p, unsigned char* __restrict__ q,
                               size_t n4) {
    quant_body((const float4*)p, (uint32_t*)q, n4, blockIdx.x, gridDim.x, 3);
}

// ============================================================
// FP8 GEMM: CTA tile 256x128x64, 256 threads, warp grid 4x2 of 64x64 tiles.
// 6-stage cp.async ring processed as PAIRS of stages: one cp.wait +
// __syncthreads per TWO K-iterations (halved barrier overhead vs R9).
// Precomputed ldsm offsets keep per-iter ALU minimal.
// ============================================================
#define BM 256
#define BN 128
#define BK 64
#define NSTAGE 6
#define STAGE_BYTES ((BM + BN) * BK)          // 24576
#define GEMM_SMEM (NSTAGE * STAGE_BYTES)      // 147456

template <bool RELU_AMAX>
__global__ __launch_bounds__(256, 1)
void gemm_fp8_kernel(const unsigned char* __restrict__ A,
                     const unsigned char* __restrict__ B,
                     float* __restrict__ C,
                     const float* __restrict__ bias,
                     int Ntot, int Ktot, int ia, int ib)
{
    extern __shared__ __align__(128) unsigned char smem[];

    const int tid = threadIdx.x;
    const int wid = tid >> 5, lane = tid & 31;
    const int m0 = blockIdx.x * BM, n0 = blockIdx.y * BN;
    const int warp_m = (wid & 3) * 64;        // 4 warps along M
    const int warp_n = (wid >> 2) * 64;       // 2 warps along N

    const uint32_t sBase = smem_u32(smem);

    // cp.async coords: 1536 16B chunks/stage, 6 per thread.
    const int cp_r = tid >> 2;                // 0..63
    const int cp_c = tid & 3;                 // 16B chunk in row
    uint32_t sAo[4], sBo[2];
    const unsigned char *gA[4], *gB[2];
    #pragma unroll
    for (int i = 0; i < 4; i++) {
        sAo[i] = soff(cp_r + 64 * i, cp_c);
        gA[i] = A + (size_t)(m0 + cp_r + 64 * i) * Ktot + cp_c * 16;
    }
    #pragma unroll
    for (int j = 0; j < 2; j++) {
        sBo[j] = soff(cp_r + 64 * j + BM, cp_c);
        gB[j] = B + (size_t)(n0 + cp_r + 64 * j) * Ktot + cp_c * 16;
    }

    // ldmatrix per-thread precomputed stage-relative offsets
    const int a_row_l = lane & 15;
    const int a_hi    = lane >> 4;
    const int b_row_l = ((lane >> 4) << 3) + (lane & 7);
    const int b_cbit  = (lane >> 3) & 1;
    uint32_t aOff[4][2], bOff[4][2];
    #pragma unroll
    for (int t = 0; t < 4; t++)
        #pragma unroll
        for (int ks = 0; ks < 2; ks++)
            aOff[t][ks] = soff(warp_m + t * 16 + a_row_l, ks * 2 + a_hi);
    #pragma unroll
    for (int p = 0; p < 4; p++)
        #pragma unroll
        for (int ks = 0; ks < 2; ks++)
            bOff[p][ks] = (uint32_t)(BM * BK) + soff(warp_n + p * 16 + b_row_l, ks * 2 + b_cbit);

    float acc[4][8][4];
    #pragma unroll
    for (int t = 0; t < 4; t++)
        #pragma unroll
        for (int n = 0; n < 8; n++)
            #pragma unroll
            for (int i = 0; i < 4; i++) acc[t][n][i] = 0.f;

    const int nK = Ktot >> 6;
    const int nK2 = nK >> 1;                  // super-iterations (pairs)

    // ---- prologue: prefetch stage-pairs 0 and 1 (stages 0..3), 2 groups ----
    #pragma unroll
    for (int g = 0; g < 2; g++) {
        #pragma unroll
        for (int shalf = 0; shalf < 2; shalf++) {
            int s = 2 * g + shalf;
            uint32_t sb = sBase + s * STAGE_BYTES;
            #pragma unroll
            for (int i = 0; i < 4; i++) CP_ASYNC16(sb + sAo[i], gA[i] + s * BK);
            #pragma unroll
            for (int j = 0; j < 2; j++) CP_ASYNC16(sb + sBo[j], gB[j] + s * BK);
        }
        CP_COMMIT();
    }

    int slot = 0;        // slot of first stage of current pair: 0,2,4,0,...
    int pslot = 4;       // slot where next prefetch pair lands: 4,0,2,4,...
    for (int it2 = 0; it2 < nK2; ++it2) {
        CP_WAIT1();
        __syncthreads();

        const uint32_t sa0 = sBase + slot * STAGE_BYTES;
        const uint32_t sa1 = sa0 + STAGE_BYTES;

        uint32_t af[4][4];
        uint32_t bf[8][2];

        // ===== stage pair, first stage: ks0 loads FIRST, then prefetch =====
        #pragma unroll
        for (int t = 0; t < 4; t++)
            ldsm_x4(af[t][0], af[t][1], af[t][2], af[t][3], sa0 + aOff[t][0]);
        #pragma unroll
        for (int p = 0; p < 4; p++) {
            uint32_t r0, r1, r2, r3;
            ldsm_x4(r0, r1, r2, r3, sa0 + bOff[p][0]);
            bf[2 * p][0] = r0;     bf[2 * p][1] = r1;
            bf[2 * p + 1][0] = r2; bf[2 * p + 1][1] = r3;
        }

        // prefetch pair it2+2 (2 stages) into pslot/pslot+1
        if (it2 + 2 < nK2) {
            size_t ko = (size_t)(2 * (it2 + 2)) * BK;
            #pragma unroll
            for (int shalf = 0; shalf < 2; shalf++) {
                uint32_t sbuf = sBase + (pslot + shalf) * STAGE_BYTES;
                #pragma unroll
                for (int i = 0; i < 4; i++) CP_ASYNC16(sbuf + sAo[i], gA[i] + ko + shalf * BK);
                #pragma unroll
                for (int j = 0; j < 2; j++) CP_ASYNC16(sbuf + sBo[j], gB[j] + ko + shalf * BK);
            }
        }
        CP_COMMIT();

        #pragma unroll
        for (int t = 0; t < 4; t++)
            #pragma unroll
            for (int n = 0; n < 8; n++)
                mma_e4m3(acc[t][n], af[t], bf[n]);

        // first stage, ks1
        #pragma unroll
        for (int t = 0; t < 4; t++)
            ldsm_x4(af[t][0], af[t][1], af[t][2], af[t][3], sa0 + aOff[t][1]);
        #pragma unroll
        for (int p = 0; p < 4; p++) {
            uint32_t r0, r1, r2, r3;
            ldsm_x4(r0, r1, r2, r3, sa0 + bOff[p][1]);
            bf[2 * p][0] = r0;     bf[2 * p][1] = r1;
            bf[2 * p + 1][0] = r2; bf[2 * p + 1][1] = r3;
        }
        #pragma unroll
        for (int t = 0; t < 4; t++)
            #pragma unroll
            for (int n = 0; n < 8; n++)
                mma_e4m3(acc[t][n], af[t], bf[n]);

        // ===== second stage of the pair (no barrier needed) =====
        #pragma unroll
        for (int ks = 0; ks < 2; ks++) {
            #pragma unroll
            for (int t = 0; t < 4; t++)
                ldsm_x4(af[t][0], af[t][1], af[t][2], af[t][3], sa1 + aOff[t][ks]);
            #pragma unroll
            for (int p = 0; p < 4; p++) {
                uint32_t r0, r1, r2, r3;
                ldsm_x4(r0, r1, r2, r3, sa1 + bOff[p][ks]);
                bf[2 * p][0] = r0;     bf[2 * p][1] = r1;
                bf[2 * p + 1][0] = r2; bf[2 * p + 1][1] = r3;
            }
            #pragma unroll
            for (int t = 0; t < 4; t++)
                #pragma unroll
                for (int n = 0; n < 8; n++)
                    mma_e4m3(acc[t][n], af[t], bf[n]);
        }

        slot += 2;  if (slot  >= NSTAGE) slot  = 0;
        pslot += 2; if (pslot >= NSTAGE) pslot = 0;
    }

    // ---- epilogue ----
    const float sa_ = 448.0f / fmaxf(g_amax[ia], 1e-12f);
    const float sb_ = 448.0f / fmaxf(g_amax[ib], 1e-12f);
    const float inv = 1.0f / (sa_ * sb_);
    const int r = lane >> 2, cq = (lane & 3) * 2;
    float lamax = 0.0f;

    #pragma unroll
    for (int t = 0; t < 4; t++) {
        #pragma unroll
        for (int n = 0; n < 8; n++) {
            int row = m0 + warp_m + t * 16 + r;
            int col = n0 + warp_n + n * 8 + cq;
            float2 bb = *(const float2*)(bias + col);
            float2 o0, o1;
            o0.x = acc[t][n][0] * inv + bb.x;
            o0.y = acc[t][n][1] * inv + bb.y;
            o1.x = acc[t][n][2] * inv + bb.x;
            o1.y = acc[t][n][3] * inv + bb.y;
            if (RELU_AMAX) {
                o0.x = fmaxf(o0.x, 0.f); o0.y = fmaxf(o0.y, 0.f);
                o1.x = fmaxf(o1.x, 0.f); o1.y = fmaxf(o1.y, 0.f);
                lamax = fmaxf(lamax, fmaxf(fmaxf(o0.x, o0.y), fmaxf(o1.x, o1.y)));
            }
            __stwt((float2*)(&C[(size_t)row * Ntot + col]), o0);
            __stwt((float2*)(&C[(size_t)(row + 8) * Ntot + col]), o1);
        }
    }
    if (RELU_AMAX) {
        for (int o = 16; o; o >>= 1) lamax = fmaxf(lamax, __shfl_xor_sync(0xffffffffu, lamax, o));
        if (lane == 0) atomicMax((int*)&g_amax[3], __float_as_int(lamax));
    }
}

// ============================================================
// Host launcher — 6 launches; gemm1 at index 3 (profiled), gemm2 at 5.
// ============================================================
extern "C" void kernel_launch(void* const* d_in, const int* in_sizes, int n_in,
                              void* d_out, int out_size) {
    const float* x  = (const float*)d_in[0];
    const float* w1 = (const float*)d_in[1];
    const float* b1 = (const float*)d_in[2];
    const float* w2 = (const float*)d_in[3];
    const float* b2 = (const float*)d_in[4];
    float* out = (float*)d_out;

    unsigned char *p_xq, *p_w1qT, *p_w2qT, *p_hq;
    float *p_h;
    cudaGetSymbolAddress((void**)&p_xq,   g_xq);
    cudaGetSymbolAddress((void**)&p_w1qT, g_w1qT);
    cudaGetSymbolAddress((void**)&p_w2qT, g_w2qT);
    cudaGetSymbolAddress((void**)&p_hq,   g_hq);
    cudaGetSymbolAddress((void**)&p_h,    g_h);

    cudaFuncSetAttribute((const void*)gemm_fp8_kernel<true>,
                         cudaFuncAttributeMaxDynamicSharedMemorySize, GEMM_SMEM);
    cudaFuncSetAttribute((const void*)gemm_fp8_kernel<false>,
                         cudaFuncAttributeMaxDynamicSharedMemorySize, GEMM_SMEM);

    init_amax_kernel<<<1, 32>>>();                                            // 0
    amax3_kernel<<<AMAX_BX + 2 * AMAX_BW, 256>>>(x, w1, w2);                  // 1
    prep_kernel<<<PREP_BLOCKS, 256>>>(x, w1, w2, p_xq, p_w1qT, p_w2qT);       // 2

    gemm_fp8_kernel<true><<<dim3(M_DIM / BM, DH / BN), 256, GEMM_SMEM>>>(     // 3
        p_xq, p_w1qT, p_h, b1, DH, DIN, 0, 1);

    quant_h_kernel<<<1184, 256>>>(p_h, p_hq, (size_t)M_DIM * DH / 4);         // 4

    gemm_fp8_kernel<false><<<dim3(M_DIM / BM, DOUT / BN), 256, GEMM_SMEM>>>(  // 5
        p_hq, p_w2qT, out, b2, DOUT, DH, 3, 2);
}

// round 12
// speedup vs baseline: 1.1106x; 1.1106x over previous
#include <cuda_runtime.h>
#include <cuda_fp8.h>
#include <cstdint>
#include <cstddef>

// ============================================================
// Dims (fixed): x[8192,4096] @ w1[4096,16384] -> relu -> @ w2[16384,4096]
// ============================================================
#define M_DIM 8192
#define DIN   4096
#define DH    16384
#define DOUT  4096

__device__ __align__(16) unsigned char g_xq  [(size_t)M_DIM * DIN];
__device__ __align__(16) unsigned char g_w1qT[(size_t)DH    * DIN];
__device__ __align__(16) unsigned char g_w2qT[(size_t)DOUT  * DH];
__device__ __align__(16) unsigned char g_hq  [(size_t)M_DIM * DH];
__device__ __align__(16) float         g_h   [(size_t)M_DIM * DH];
__device__ float g_amax[4];   // 0:x 1:w1 2:w2 3:h

// ============================================================
// PTX helpers (base sm_103-legal only)
// ============================================================
__device__ __forceinline__ uint32_t smem_u32(const void* p) {
    uint32_t a;
    asm("{ .reg .u64 t; cvta.to.shared.u64 t, %1; cvt.u32.u64 %0, t; }" : "=r"(a) : "l"(p));
    return a;
}

#define CP_ASYNC16(saddr, gptr) \
    asm volatile("cp.async.cg.shared.global [%0], [%1], 16;\n" :: "r"(saddr), "l"(gptr))
#define CP_COMMIT() asm volatile("cp.async.commit_group;\n" ::: "memory")
#define CP_WAIT2()  asm volatile("cp.async.wait_group 2;\n" ::: "memory")

__device__ __forceinline__ void ldsm_x4(uint32_t& r0, uint32_t& r1, uint32_t& r2, uint32_t& r3,
                                        uint32_t addr) {
    asm volatile("ldmatrix.sync.aligned.m8n8.x4.shared.b16 {%0,%1,%2,%3}, [%4];\n"
                 : "=r"(r0), "=r"(r1), "=r"(r2), "=r"(r3) : "r"(addr));
}

__device__ __forceinline__ void mma_e4m3(float* d, const uint32_t* a, const uint32_t* b) {
    asm volatile(
        "mma.sync.aligned.m16n8k32.row.col.f32.e4m3.e4m3.f32 "
        "{%0,%1,%2,%3}, {%4,%5,%6,%7}, {%8,%9}, {%0,%1,%2,%3};\n"
        : "+f"(d[0]), "+f"(d[1]), "+f"(d[2]), "+f"(d[3])
        : "r"(a[0]), "r"(a[1]), "r"(a[2]), "r"(a[3]), "r"(b[0]), "r"(b[1]));
}

// SMEM tile rows of 64B (BK=64); 16B chunk idx XOR-swizzled by (row>>1)&3.
__device__ __forceinline__ uint32_t soff(int r, int c16) {
    return (uint32_t)(r * 64 + (((c16) ^ ((r >> 1) & 3)) << 4));
}

// ============================================================
// init / amax / quant / transpose-quant bodies
// ============================================================
__global__ void init_amax_kernel() {
    if (threadIdx.x < 4) g_amax[threadIdx.x] = 0.0f;
}

__device__ __forceinline__ void amax_body(const float4* __restrict__ p4, size_t n4,
                                          int rb, int nb, int slot) {
    float m = 0.f;
    size_t i0 = (size_t)rb * blockDim.x + threadIdx.x;
    size_t stride = (size_t)nb * blockDim.x;
    for (size_t i = i0; i < n4; i += stride) {
        float4 v = __ldcs(p4 + i);
        m = fmaxf(m, fmaxf(fmaxf(fabsf(v.x), fabsf(v.y)), fmaxf(fabsf(v.z), fabsf(v.w))));
    }
    for (int o = 16; o; o >>= 1) m = fmaxf(m, __shfl_xor_sync(0xffffffffu, m, o));
    __shared__ float sm[8];
    if ((threadIdx.x & 31) == 0) sm[threadIdx.x >> 5] = m;
    __syncthreads();
    if (threadIdx.x < 32) {
        m = (threadIdx.x < (blockDim.x >> 5)) ? sm[threadIdx.x] : 0.f;
        for (int o = 16; o; o >>= 1) m = fmaxf(m, __shfl_xor_sync(0xffffffffu, m, o));
        if (threadIdx.x == 0) atomicMax((int*)&g_amax[slot], __float_as_int(m));
    }
}

// Main-stream: amax over x and w1 only
#define AMAX_BX 320
#define AMAX_BW 640
__global__ void amax2_kernel(const float* __restrict__ x,
                             const float* __restrict__ w1) {
    int b = blockIdx.x;
    if (b < AMAX_BX) {
        amax_body((const float4*)x, (size_t)M_DIM * DIN / 4, b, AMAX_BX, 0);
    } else {
        amax_body((const float4*)w1, (size_t)DIN * DH / 4, b - AMAX_BX, AMAX_BW, 1);
    }
}

// Side-stream: amax over w2
__global__ void amax_w2_kernel(const float* __restrict__ w2) {
    amax_body((const float4*)w2, (size_t)DH * DOUT / 4, blockIdx.x, gridDim.x, 2);
}

__device__ __forceinline__ void quant_body(const float4* __restrict__ p4,
                                           uint32_t* __restrict__ q4,
                                           size_t n4, int rb, int nb, int slot) {
    float s = 448.0f / fmaxf(g_amax[slot], 1e-12f);
    size_t i0 = (size_t)rb * blockDim.x + threadIdx.x;
    size_t stride = (size_t)nb * blockDim.x;
    for (size_t i = i0; i < n4; i += stride) {
        float4 v = __ldcs(p4 + i);
        __nv_fp8x2_storage_t lo = __nv_cvt_float2_to_fp8x2(make_float2(v.x * s, v.y * s), __NV_SATFINITE, __NV_E4M3);
        __nv_fp8x2_storage_t hi = __nv_cvt_float2_to_fp8x2(make_float2(v.z * s, v.w * s), __NV_SATFINITE, __NV_E4M3);
        q4[i] = (uint32_t)lo | ((uint32_t)hi << 16);
    }
}

__device__ __forceinline__ void quantT_body(const float* __restrict__ w,
                                            unsigned char* __restrict__ qT,
                                            int K, int N, int n0, int k0, int slot) {
    __shared__ float tile[32][33];
    float s = 448.0f / fmaxf(g_amax[slot], 1e-12f);
    int tx = threadIdx.x & 31, ty = threadIdx.x >> 5;
    #pragma unroll
    for (int r = ty; r < 32; r += 8)
        tile[r][tx] = __ldcs(&w[(size_t)(k0 + r) * N + n0 + tx]);
    __syncthreads();
    #pragma unroll
    for (int r = ty; r < 32; r += 8) {
        float v = tile[tx][r] * s;
        qT[(size_t)(n0 + r) * K + k0 + tx] =
            __nv_cvt_float_to_fp8(v, __NV_SATFINITE, __NV_E4M3);
    }
}

// Main-stream prep: quant(x) + transpose-quant(w1)
#define PREP_QX   1184
#define PREP_W1T  ((DH / 32) * (DIN / 32))    // 65536
#define PREP2_BLOCKS (PREP_QX + PREP_W1T)

__global__ void prep2_kernel(const float* __restrict__ x,
                             const float* __restrict__ w1,
                             unsigned char* __restrict__ xq,
                             unsigned char* __restrict__ w1qT) {
    int b = blockIdx.x;
    if (b < PREP_QX) {
        quant_body((const float4*)x, (uint32_t*)xq, (size_t)M_DIM * DIN / 4, b, PREP_QX, 0);
    } else {
        int t = b - PREP_QX;
        int n0 = (t % (DH / 32)) * 32, k0 = (t / (DH / 32)) * 32;
        quantT_body(w1, w1qT, DIN, DH, n0, k0, 1);
    }
}

// Side-stream: transpose-quant(w2)
#define PREP_W2T  ((DOUT / 32) * (DH / 32))   // 65536
__global__ void quantT_w2_kernel(const float* __restrict__ w2,
                                 unsigned char* __restrict__ w2qT) {
    int t = blockIdx.x;
    int n0 = (t % (DOUT / 32)) * 32, k0 = (t / (DOUT / 32)) * 32;
    quantT_body(w2, w2qT, DH, DOUT, n0, k0, 2);
}

__global__ void quant_h_kernel(const float* __restrict__ p, unsigned char* __restrict__ q,
                               size_t n4) {
    quant_body((const float4*)p, (uint32_t*)q, n4, blockIdx.x, gridDim.x, 3);
}

// ============================================================
// FP8 GEMM (R9 winner, verbatim): CTA 256x128x64, 256 threads, warp grid
// 4x2 of 64x64 tiles, 4-stage cp.async ring; ldsm(ks0) issued before the
// global prefetch so fragment loads lead the L1tex queue.
// ============================================================
#define BM 256
#define BN 128
#define BK 64
#define NSTAGE 4
#define STAGE_BYTES ((BM + BN) * BK)          // 24576
#define GEMM_SMEM (NSTAGE * STAGE_BYTES)      // 98304

template <bool RELU_AMAX>
__global__ __launch_bounds__(256, 1)
void gemm_fp8_kernel(const unsigned char* __restrict__ A,
                     const unsigned char* __restrict__ B,
                     float* __restrict__ C,
                     const float* __restrict__ bias,
                     int Ntot, int Ktot, int ia, int ib)
{
    extern __shared__ __align__(128) unsigned char smem[];

    const int tid = threadIdx.x;
    const int wid = tid >> 5, lane = tid & 31;
    const int m0 = blockIdx.x * BM, n0 = blockIdx.y * BN;
    const int warp_m = (wid & 3) * 64;        // 4 warps along M
    const int warp_n = (wid >> 2) * 64;       // 2 warps along N

    const uint32_t sBase = smem_u32(smem);

    const int cp_r = tid >> 2;                // 0..63
    const int cp_c = tid & 3;                 // 16B chunk in row
    uint32_t sA[4], sB[2];
    const unsigned char *gA[4], *gB[2];
    #pragma unroll
    for (int i = 0; i < 4; i++) {
        sA[i] = soff(cp_r + 64 * i, cp_c);
        gA[i] = A + (size_t)(m0 + cp_r + 64 * i) * Ktot + cp_c * 16;
    }
    #pragma unroll
    for (int j = 0; j < 2; j++) {
        sB[j] = soff(cp_r + 64 * j + BM, cp_c);
        gB[j] = B + (size_t)(n0 + cp_r + 64 * j) * Ktot + cp_c * 16;
    }

    const int a_row_l = lane & 15;
    const int a_hi    = lane >> 4;
    const int b_row_l = ((lane >> 4) << 3) + (lane & 7);
    const int b_cbit  = (lane >> 3) & 1;

    float acc[4][8][4];
    #pragma unroll
    for (int t = 0; t < 4; t++)
        #pragma unroll
        for (int n = 0; n < 8; n++)
            #pragma unroll
            for (int i = 0; i < 4; i++) acc[t][n][i] = 0.f;

    const int nK = Ktot >> 6;

    #pragma unroll
    for (int s = 0; s < NSTAGE - 1; s++) {
        uint32_t sb = sBase + s * STAGE_BYTES;
        #pragma unroll
        for (int i = 0; i < 4; i++) CP_ASYNC16(sb + sA[i], gA[i] + s * BK);
        #pragma unroll
        for (int j = 0; j < 2; j++) CP_ASYNC16(sb + sB[j], gB[j] + s * BK);
        CP_COMMIT();
    }

    for (int it = 0; it < nK; ++it) {
        CP_WAIT2();
        __syncthreads();

        const uint32_t sa = sBase + (it & (NSTAGE - 1)) * STAGE_BYTES;
        const uint32_t sb = sa + BM * BK;

        // ---- ks = 0: fragment loads FIRST (ahead of global prefetch) ----
        uint32_t af[4][4];
        uint32_t bf[8][2];
        #pragma unroll
        for (int t = 0; t < 4; t++) {
            int r = warp_m + t * 16 + a_row_l;
            ldsm_x4(af[t][0], af[t][1], af[t][2], af[t][3], sa + soff(r, a_hi));
        }
        #pragma unroll
        for (int p = 0; p < 4; p++) {
            int r = warp_n + p * 16 + b_row_l;
            uint32_t r0, r1, r2, r3;
            ldsm_x4(r0, r1, r2, r3, sb + soff(r, b_cbit));
            bf[2 * p][0] = r0;     bf[2 * p][1] = r1;
            bf[2 * p + 1][0] = r2; bf[2 * p + 1][1] = r3;
        }

        // ---- prefetch next stage (overlaps ks0 MMAs) ----
        if (it + NSTAGE - 1 < nK) {
            int s = (it + NSTAGE - 1) & (NSTAGE - 1);
            uint32_t sbuf = sBase + s * STAGE_BYTES;
            size_t ko = (size_t)(it + NSTAGE - 1) * BK;
            #pragma unroll
            for (int i = 0; i < 4; i++) CP_ASYNC16(sbuf + sA[i], gA[i] + ko);
            #pragma unroll
            for (int j = 0; j < 2; j++) CP_ASYNC16(sbuf + sB[j], gB[j] + ko);
        }
        CP_COMMIT();

        // ---- ks = 0 MMAs ----
        #pragma unroll
        for (int t = 0; t < 4; t++)
            #pragma unroll
            for (int n = 0; n < 8; n++)
                mma_e4m3(acc[t][n], af[t], bf[n]);

        // ---- ks = 1: loads then MMAs ----
        #pragma unroll
        for (int t = 0; t < 4; t++) {
            int r = warp_m + t * 16 + a_row_l;
            ldsm_x4(af[t][0], af[t][1], af[t][2], af[t][3], sa + soff(r, 2 + a_hi));
        }
        #pragma unroll
        for (int p = 0; p < 4; p++) {
            int r = warp_n + p * 16 + b_row_l;
            uint32_t r0, r1, r2, r3;
            ldsm_x4(r0, r1, r2, r3, sb + soff(r, 2 + b_cbit));
            bf[2 * p][0] = r0;     bf[2 * p][1] = r1;
            bf[2 * p + 1][0] = r2; bf[2 * p + 1][1] = r3;
        }
        #pragma unroll
        for (int t = 0; t < 4; t++)
            #pragma unroll
            for (int n = 0; n < 8; n++)
                mma_e4m3(acc[t][n], af[t], bf[n]);
    }

    // ---- epilogue ----
    const float sa_ = 448.0f / fmaxf(g_amax[ia], 1e-12f);
    const float sb_ = 448.0f / fmaxf(g_amax[ib], 1e-12f);
    const float inv = 1.0f / (sa_ * sb_);
    const int r = lane >> 2, cq = (lane & 3) * 2;
    float lamax = 0.0f;

    #pragma unroll
    for (int t = 0; t < 4; t++) {
        #pragma unroll
        for (int n = 0; n < 8; n++) {
            int row = m0 + warp_m + t * 16 + r;
            int col = n0 + warp_n + n * 8 + cq;
            float2 bb = *(const float2*)(bias + col);
            float2 o0, o1;
            o0.x = acc[t][n][0] * inv + bb.x;
            o0.y = acc[t][n][1] * inv + bb.y;
            o1.x = acc[t][n][2] * inv + bb.x;
            o1.y = acc[t][n][3] * inv + bb.y;
            if (RELU_AMAX) {
                o0.x = fmaxf(o0.x, 0.f); o0.y = fmaxf(o0.y, 0.f);
                o1.x = fmaxf(o1.x, 0.f); o1.y = fmaxf(o1.y, 0.f);
                lamax = fmaxf(lamax, fmaxf(fmaxf(o0.x, o0.y), fmaxf(o1.x, o1.y)));
            }
            __stwt((float2*)(&C[(size_t)row * Ntot + col]), o0);
            __stwt((float2*)(&C[(size_t)(row + 8) * Ntot + col]), o1);
        }
    }
    if (RELU_AMAX) {
        for (int o = 16; o; o >>= 1) lamax = fmaxf(lamax, __shfl_xor_sync(0xffffffffu, lamax, o));
        if (lane == 0) atomicMax((int*)&g_amax[3], __float_as_int(lamax));
    }
}

// ============================================================
// Host launcher — graph-capture fork: w2 prep overlaps gemm1.
//   main:  init → amax2(x,w1) → prep2 → gemm1 → quant_h → [join] → gemm2
//   side:  [fork after init] amax(w2) → quantT(w2)
// ============================================================
extern "C" void kernel_launch(void* const* d_in, const int* in_sizes, int n_in,
                              void* d_out, int out_size) {
    const float* x  = (const float*)d_in[0];
    const float* w1 = (const float*)d_in[1];
    const float* b1 = (const float*)d_in[2];
    const float* w2 = (const float*)d_in[3];
    const float* b2 = (const float*)d_in[4];
    float* out = (float*)d_out;

    unsigned char *p_xq, *p_w1qT, *p_w2qT, *p_hq;
    float *p_h;
    cudaGetSymbolAddress((void**)&p_xq,   g_xq);
    cudaGetSymbolAddress((void**)&p_w1qT, g_w1qT);
    cudaGetSymbolAddress((void**)&p_w2qT, g_w2qT);
    cudaGetSymbolAddress((void**)&p_hq,   g_hq);
    cudaGetSymbolAddress((void**)&p_h,    g_h);

    static cudaStream_t s2 = nullptr;
    static cudaEvent_t eFork = nullptr, eJoin = nullptr;
    if (s2 == nullptr) {   // created on the first (non-captured) correctness call
        cudaStreamCreateWithFlags(&s2, cudaStreamNonBlocking);
        cudaEventCreateWithFlags(&eFork, cudaEventDisableTiming);
        cudaEventCreateWithFlags(&eJoin, cudaEventDisableTiming);
        cudaFuncSetAttribute((const void*)gemm_fp8_kernel<true>,
                             cudaFuncAttributeMaxDynamicSharedMemorySize, GEMM_SMEM);
        cudaFuncSetAttribute((const void*)gemm_fp8_kernel<false>,
                             cudaFuncAttributeMaxDynamicSharedMemorySize, GEMM_SMEM);
    }

    // main stream (legacy default)
    init_amax_kernel<<<1, 32>>>();

    // fork side stream: w2 amax + transpose-quant (consumed only by gemm2)
    cudaEventRecord(eFork, 0);
    cudaStreamWaitEvent(s2, eFork, 0);
    amax_w2_kernel<<<296, 256, 0, s2>>>(w2);
    quantT_w2_kernel<<<PREP_W2T, 256, 0, s2>>>(w2, p_w2qT);
    cudaEventRecord(eJoin, s2);

    // main chain
    amax2_kernel<<<AMAX_BX + AMAX_BW, 256>>>(x, w1);
    prep2_kernel<<<PREP2_BLOCKS, 256>>>(x, w1, p_xq, p_w1qT);

    gemm_fp8_kernel<true><<<dim3(M_DIM / BM, DH / BN), 256, GEMM_SMEM>>>(
        p_xq, p_w1qT, p_h, b1, DH, DIN, 0, 1);

    quant_h_kernel<<<1184, 256>>>(p_h, p_hq, (size_t)M_DIM * DH / 4);

    cudaStreamWaitEvent(0, eJoin, 0);   // join w2 branch
    gemm_fp8_kernel<false><<<dim3(M_DIM / BM, DOUT / BN), 256, GEMM_SMEM>>>(
        p_hq, p_w2qT, out, b2, DOUT, DH, 3, 2);
}

// round 14
// speedup vs baseline: 1.1121x; 1.0014x over previous
#include <cuda_runtime.h>
#include <cuda_fp8.h>
#include <cstdint>
#include <cstddef>

// ============================================================
// Dims (fixed): x[8192,4096] @ w1[4096,16384] -> relu -> @ w2[16384,4096]
// ============================================================
#define M_DIM 8192
#define DIN   4096
#define DH    16384
#define DOUT  4096

__device__ __align__(16) unsigned char g_xq  [(size_t)M_DIM * DIN];
__device__ __align__(16) unsigned char g_w1qT[(size_t)DH    * DIN];
__device__ __align__(16) unsigned char g_w2qT[(size_t)DOUT  * DH];
__device__ __align__(16) unsigned char g_hq  [(size_t)M_DIM * DH];
__device__ __align__(16) float         g_h   [(size_t)M_DIM * DH];   // fp32: exact (bf16 broke e4m3 binning)
__device__ float g_amax[4];   // 0:x 1:w1 2:w2 3:h

// ============================================================
// PTX helpers (base sm_103-legal only)
// ============================================================
__device__ __forceinline__ uint32_t smem_u32(const void* p) {
    uint32_t a;
    asm("{ .reg .u64 t; cvta.to.shared.u64 t, %1; cvt.u32.u64 %0, t; }" : "=r"(a) : "l"(p));
    return a;
}

#define CP_ASYNC16(saddr, gptr) \
    asm volatile("cp.async.cg.shared.global [%0], [%1], 16;\n" :: "r"(saddr), "l"(gptr))
#define CP_COMMIT() asm volatile("cp.async.commit_group;\n" ::: "memory")
#define CP_WAIT2()  asm volatile("cp.async.wait_group 2;\n" ::: "memory")

__device__ __forceinline__ void ldsm_x4(uint32_t& r0, uint32_t& r1, uint32_t& r2, uint32_t& r3,
                                        uint32_t addr) {
    asm volatile("ldmatrix.sync.aligned.m8n8.x4.shared.b16 {%0,%1,%2,%3}, [%4];\n"
                 : "=r"(r0), "=r"(r1), "=r"(r2), "=r"(r3) : "r"(addr));
}

__device__ __forceinline__ void mma_e4m3(float* d, const uint32_t* a, const uint32_t* b) {
    asm volatile(
        "mma.sync.aligned.m16n8k32.row.col.f32.e4m3.e4m3.f32 "
        "{%0,%1,%2,%3}, {%4,%5,%6,%7}, {%8,%9}, {%0,%1,%2,%3};\n"
        : "+f"(d[0]), "+f"(d[1]), "+f"(d[2]), "+f"(d[3])
        : "r"(a[0]), "r"(a[1]), "r"(a[2]), "r"(a[3]), "r"(b[0]), "r"(b[1]));
}

// SMEM tile rows of 64B (BK=64); 16B chunk idx XOR-swizzled by (row>>1)&3.
__device__ __forceinline__ uint32_t soff(int r, int c16) {
    return (uint32_t)(r * 64 + (((c16) ^ ((r >> 1) & 3)) << 4));
}

// ============================================================
// init / amax / quant / transpose-quant bodies
// ============================================================
__global__ void init_amax_kernel() {
    if (threadIdx.x < 4) g_amax[threadIdx.x] = 0.0f;
}

__device__ __forceinline__ void amax_body(const float4* __restrict__ p4, size_t n4,
                                          int rb, int nb, int slot) {
    float m = 0.f;
    size_t i0 = (size_t)rb * blockDim.x + threadIdx.x;
    size_t stride = (size_t)nb * blockDim.x;
    for (size_t i = i0; i < n4; i += stride) {
        float4 v = __ldcs(p4 + i);
        m = fmaxf(m, fmaxf(fmaxf(fabsf(v.x), fabsf(v.y)), fmaxf(fabsf(v.z), fabsf(v.w))));
    }
    for (int o = 16; o; o >>= 1) m = fmaxf(m, __shfl_xor_sync(0xffffffffu, m, o));
    __shared__ float sm[8];
    if ((threadIdx.x & 31) == 0) sm[threadIdx.x >> 5] = m;
    __syncthreads();
    if (threadIdx.x < 32) {
        m = (threadIdx.x < (blockDim.x >> 5)) ? sm[threadIdx.x] : 0.f;
        for (int o = 16; o; o >>= 1) m = fmaxf(m, __shfl_xor_sync(0xffffffffu, m, o));
        if (threadIdx.x == 0) atomicMax((int*)&g_amax[slot], __float_as_int(m));
    }
}

#define AMAX_BX 320
#define AMAX_BW 640
__global__ void amax2_kernel(const float* __restrict__ x,
                             const float* __restrict__ w1) {
    int b = blockIdx.x;
    if (b < AMAX_BX) {
        amax_body((const float4*)x, (size_t)M_DIM * DIN / 4, b, AMAX_BX, 0);
    } else {
        amax_body((const float4*)w1, (size_t)DIN * DH / 4, b - AMAX_BX, AMAX_BW, 1);
    }
}

__global__ void amax_w2_kernel(const float* __restrict__ w2) {
    amax_body((const float4*)w2, (size_t)DH * DOUT / 4, blockIdx.x, gridDim.x, 2);
}

__device__ __forceinline__ void quant_body(const float4* __restrict__ p4,
                                           uint32_t* __restrict__ q4,
                                           size_t n4, int rb, int nb, int slot) {
    float s = 448.0f / fmaxf(g_amax[slot], 1e-12f);
    size_t i0 = (size_t)rb * blockDim.x + threadIdx.x;
    size_t stride = (size_t)nb * blockDim.x;
    for (size_t i = i0; i < n4; i += stride) {
        float4 v = __ldcs(p4 + i);
        __nv_fp8x2_storage_t lo = __nv_cvt_float2_to_fp8x2(make_float2(v.x * s, v.y * s), __NV_SATFINITE, __NV_E4M3);
        __nv_fp8x2_storage_t hi = __nv_cvt_float2_to_fp8x2(make_float2(v.z * s, v.w * s), __NV_SATFINITE, __NV_E4M3);
        q4[i] = (uint32_t)lo | ((uint32_t)hi << 16);
    }
}

__device__ __forceinline__ void quantT_body(const float* __restrict__ w,
                                            unsigned char* __restrict__ qT,
                                            int K, int N, int n0, int k0, int slot) {
    __shared__ float tile[32][33];
    float s = 448.0f / fmaxf(g_amax[slot], 1e-12f);
    int tx = threadIdx.x & 31, ty = threadIdx.x >> 5;
    #pragma unroll
    for (int r = ty; r < 32; r += 8)
        tile[r][tx] = __ldcs(&w[(size_t)(k0 + r) * N + n0 + tx]);
    __syncthreads();
    #pragma unroll
    for (int r = ty; r < 32; r += 8) {
        float v = tile[tx][r] * s;
        qT[(size_t)(n0 + r) * K + k0 + tx] =
            __nv_cvt_float_to_fp8(v, __NV_SATFINITE, __NV_E4M3);
    }
}

#define PREP_QX   1184
#define PREP_W1T  ((DH / 32) * (DIN / 32))    // 65536
#define PREP2_BLOCKS (PREP_QX + PREP_W1T)

__global__ void prep2_kernel(const float* __restrict__ x,
                             const float* __restrict__ w1,
                             unsigned char* __restrict__ xq,
                             unsigned char* __restrict__ w1qT) {
    int b = blockIdx.x;
    if (b < PREP_QX) {
        quant_body((const float4*)x, (uint32_t*)xq, (size_t)M_DIM * DIN / 4, b, PREP_QX, 0);
    } else {
        int t = b - PREP_QX;
        int n0 = (t % (DH / 32)) * 32, k0 = (t / (DH / 32)) * 32;
        quantT_body(w1, w1qT, DIN, DH, n0, k0, 1);
    }
}

#define PREP_W2T  ((DOUT / 32) * (DH / 32))   // 65536
__global__ void quantT_w2_kernel(const float* __restrict__ w2,
                                 unsigned char* __restrict__ w2qT) {
    int t = blockIdx.x;
    int n0 = (t % (DOUT / 32)) * 32, k0 = (t / (DOUT / 32)) * 32;
    quantT_body(w2, w2qT, DH, DOUT, n0, k0, 2);
}

__global__ void quant_h_kernel(const float* __restrict__ p, unsigned char* __restrict__ q,
                               size_t n4) {
    quant_body((const float4*)p, (uint32_t*)q, n4, blockIdx.x, gridDim.x, 3);
}

// ============================================================
// FP8 GEMM (R9 winner, verbatim): CTA 256x128x64, 256 threads, warp grid
// 4x2 of 64x64 tiles, 4-stage cp.async ring; ldsm(ks0) ahead of global
// prefetch so fragment loads lead the L1tex queue.
// ============================================================
#define BM 256
#define BN 128
#define BK 64
#define NSTAGE 4
#define STAGE_BYTES ((BM + BN) * BK)          // 24576
#define GEMM_SMEM (NSTAGE * STAGE_BYTES)      // 98304

template <bool RELU_AMAX>
__global__ __launch_bounds__(256, 1)
void gemm_fp8_kernel(const unsigned char* __restrict__ A,
                     const unsigned char* __restrict__ B,
                     float* __restrict__ C,
                     const float* __restrict__ bias,
                     int Ntot, int Ktot, int ia, int ib)
{
    extern __shared__ __align__(128) unsigned char smem[];

    const int tid = threadIdx.x;
    const int wid = tid >> 5, lane = tid & 31;
    const int m0 = blockIdx.x * BM, n0 = blockIdx.y * BN;
    const int warp_m = (wid & 3) * 64;        // 4 warps along M
    const int warp_n = (wid >> 2) * 64;       // 2 warps along N

    const uint32_t sBase = smem_u32(smem);

    const int cp_r = tid >> 2;                // 0..63
    const int cp_c = tid & 3;                 // 16B chunk in row
    uint32_t sA[4], sB[2];
    const unsigned char *gA[4], *gB[2];
    #pragma unroll
    for (int i = 0; i < 4; i++) {
        sA[i] = soff(cp_r + 64 * i, cp_c);
        gA[i] = A + (size_t)(m0 + cp_r + 64 * i) * Ktot + cp_c * 16;
    }
    #pragma unroll
    for (int j = 0; j < 2; j++) {
        sB[j] = soff(cp_r + 64 * j + BM, cp_c);
        gB[j] = B + (size_t)(n0 + cp_r + 64 * j) * Ktot + cp_c * 16;
    }

    const int a_row_l = lane & 15;
    const int a_hi    = lane >> 4;
    const int b_row_l = ((lane >> 4) << 3) + (lane & 7);
    const int b_cbit  = (lane >> 3) & 1;

    float acc[4][8][4];
    #pragma unroll
    for (int t = 0; t < 4; t++)
        #pragma unroll
        for (int n = 0; n < 8; n++)
            #pragma unroll
            for (int i = 0; i < 4; i++) acc[t][n][i] = 0.f;

    const int nK = Ktot >> 6;

    #pragma unroll
    for (int s = 0; s < NSTAGE - 1; s++) {
        uint32_t sb = sBase + s * STAGE_BYTES;
        #pragma unroll
        for (int i = 0; i < 4; i++) CP_ASYNC16(sb + sA[i], gA[i] + s * BK);
        #pragma unroll
        for (int j = 0; j < 2; j++) CP_ASYNC16(sb + sB[j], gB[j] + s * BK);
        CP_COMMIT();
    }

    for (int it = 0; it < nK; ++it) {
        CP_WAIT2();
        __syncthreads();

        const uint32_t sa = sBase + (it & (NSTAGE - 1)) * STAGE_BYTES;
        const uint32_t sb = sa + BM * BK;

        // ---- ks = 0: fragment loads FIRST (ahead of global prefetch) ----
        uint32_t af[4][4];
        uint32_t bf[8][2];
        #pragma unroll
        for (int t = 0; t < 4; t++) {
            int r = warp_m + t * 16 + a_row_l;
            ldsm_x4(af[t][0], af[t][1], af[t][2], af[t][3], sa + soff(r, a_hi));
        }
        #pragma unroll
        for (int p = 0; p < 4; p++) {
            int r = warp_n + p * 16 + b_row_l;
            uint32_t r0, r1, r2, r3;
            ldsm_x4(r0, r1, r2, r3, sb + soff(r, b_cbit));
            bf[2 * p][0] = r0;     bf[2 * p][1] = r1;
            bf[2 * p + 1][0] = r2; bf[2 * p + 1][1] = r3;
        }

        // ---- prefetch next stage (overlaps ks0 MMAs) ----
        if (it + NSTAGE - 1 < nK) {
            int s = (it + NSTAGE - 1) & (NSTAGE - 1);
            uint32_t sbuf = sBase + s * STAGE_BYTES;
            size_t ko = (size_t)(it + NSTAGE - 1) * BK;
            #pragma unroll
            for (int i = 0; i < 4; i++) CP_ASYNC16(sbuf + sA[i], gA[i] + ko);
            #pragma unroll
            for (int j = 0; j < 2; j++) CP_ASYNC16(sbuf + sB[j], gB[j] + ko);
        }
        CP_COMMIT();

        // ---- ks = 0 MMAs ----
        #pragma unroll
        for (int t = 0; t < 4; t++)
            #pragma unroll
            for (int n = 0; n < 8; n++)
                mma_e4m3(acc[t][n], af[t], bf[n]);

        // ---- ks = 1: loads then MMAs ----
        #pragma unroll
        for (int t = 0; t < 4; t++) {
            int r = warp_m + t * 16 + a_row_l;
            ldsm_x4(af[t][0], af[t][1], af[t][2], af[t][3], sa + soff(r, 2 + a_hi));
        }
        #pragma unroll
        for (int p = 0; p < 4; p++) {
            int r = warp_n + p * 16 + b_row_l;
            uint32_t r0, r1, r2, r3;
            ldsm_x4(r0, r1, r2, r3, sb + soff(r, 2 + b_cbit));
            bf[2 * p][0] = r0;     bf[2 * p][1] = r1;
            bf[2 * p + 1][0] = r2; bf[2 * p + 1][1] = r3;
        }
        #pragma unroll
        for (int t = 0; t < 4; t++)
            #pragma unroll
            for (int n = 0; n < 8; n++)
                mma_e4m3(acc[t][n], af[t], bf[n]);
    }

    // ---- epilogue ----
    const float sa_ = 448.0f / fmaxf(g_amax[ia], 1e-12f);
    const float sb_ = 448.0f / fmaxf(g_amax[ib], 1e-12f);
    const float inv = 1.0f / (sa_ * sb_);
    const int r = lane >> 2, cq = (lane & 3) * 2;
    float lamax = 0.0f;

    #pragma unroll
    for (int t = 0; t < 4; t++) {
        #pragma unroll
        for (int n = 0; n < 8; n++) {
            int row = m0 + warp_m + t * 16 + r;
            int col = n0 + warp_n + n * 8 + cq;
            float2 bb = *(const float2*)(bias + col);
            float2 o0, o1;
            o0.x = acc[t][n][0] * inv + bb.x;
            o0.y = acc[t][n][1] * inv + bb.y;
            o1.x = acc[t][n][2] * inv + bb.x;
            o1.y = acc[t][n][3] * inv + bb.y;
            if (RELU_AMAX) {
                o0.x = fmaxf(o0.x, 0.f); o0.y = fmaxf(o0.y, 0.f);
                o1.x = fmaxf(o1.x, 0.f); o1.y = fmaxf(o1.y, 0.f);
                lamax = fmaxf(lamax, fmaxf(fmaxf(o0.x, o0.y), fmaxf(o1.x, o1.y)));
            }
            __stwt((float2*)(&C[(size_t)row * Ntot + col]), o0);
            __stwt((float2*)(&C[(size_t)(row + 8) * Ntot + col]), o1);
        }
    }
    if (RELU_AMAX) {
        for (int o = 16; o; o >>= 1) lamax = fmaxf(lamax, __shfl_xor_sync(0xffffffffu, lamax, o));
        if (lane == 0) atomicMax((int*)&g_amax[3], __float_as_int(lamax));
    }
}

// ============================================================
// Host launcher — delayed fork: w2 prep overlaps gemm1 (DRAM idle there).
//   main:  init → amax2(x,w1) → prep2 → [fork] gemm1 → quant_h → [join] → gemm2
//   side:  [waits for fork] amax(w2) → quantT(w2)
// ============================================================
extern "C" void kernel_launch(void* const* d_in, const int* in_sizes, int n_in,
                              void* d_out, int out_size) {
    const float* x  = (const float*)d_in[0];
    const float* w1 = (const float*)d_in[1];
    const float* b1 = (const float*)d_in[2];
    const float* w2 = (const float*)d_in[3];
    const float* b2 = (const float*)d_in[4];
    float* out = (float*)d_out;

    unsigned char *p_xq, *p_w1qT, *p_w2qT, *p_hq;
    float *p_h;
    cudaGetSymbolAddress((void**)&p_xq,   g_xq);
    cudaGetSymbolAddress((void**)&p_w1qT, g_w1qT);
    cudaGetSymbolAddress((void**)&p_w2qT, g_w2qT);
    cudaGetSymbolAddress((void**)&p_hq,   g_hq);
    cudaGetSymbolAddress((void**)&p_h,    g_h);

    static cudaStream_t s2 = nullptr;
    static cudaEvent_t eFork = nullptr, eJoin = nullptr;
    if (s2 == nullptr) {   // created on the first (non-captured) correctness call
        cudaStreamCreateWithFlags(&s2, cudaStreamNonBlocking);
        cudaEventCreateWithFlags(&eFork, cudaEventDisableTiming);
        cudaEventCreateWithFlags(&eJoin, cudaEventDisableTiming);
        cudaFuncSetAttribute((const void*)gemm_fp8_kernel<true>,
                             cudaFuncAttributeMaxDynamicSharedMemorySize, GEMM_SMEM);
        cudaFuncSetAttribute((const void*)gemm_fp8_kernel<false>,
                             cudaFuncAttributeMaxDynamicSharedMemorySize, GEMM_SMEM);
    }

    // main chain: DRAM-bound prep first (no competition)
    init_amax_kernel<<<1, 32>>>();
    amax2_kernel<<<AMAX_BX + AMAX_BW, 256>>>(x, w1);
    prep2_kernel<<<PREP2_BLOCKS, 256>>>(x, w1, p_xq, p_w1qT);

    // fork AFTER prep2: side-stream w2 work overlaps gemm1 (DRAM idle)
    cudaEventRecord(eFork, 0);
    cudaStreamWaitEvent(s2, eFork, 0);
    amax_w2_kernel<<<296, 256, 0, s2>>>(w2);
    quantT_w2_kernel<<<PREP_W2T, 256, 0, s2>>>(w2, p_w2qT);
    cudaEventRecord(eJoin, s2);

    gemm_fp8_kernel<true><<<dim3(M_DIM / BM, DH / BN), 256, GEMM_SMEM>>>(
        p_xq, p_w1qT, p_h, b1, DH, DIN, 0, 1);

    quant_h_kernel<<<1184, 256>>>(p_h, p_hq, (size_t)M_DIM * DH / 4);

    cudaStreamWaitEvent(0, eJoin, 0);   // join w2 branch
    gemm_fp8_kernel<false><<<dim3(M_DIM / BM, DOUT / BN), 256, GEMM_SMEM>>>(
        p_hq, p_w2qT, out, b2, DOUT, DH, 3, 2);
}